// round 1
// baseline (speedup 1.0000x reference)
#include <cuda_runtime.h>

#define B_ 8
#define N_ 2500
#define E_ 100
#define F_ 50
#define Y_ 8922
#define V_ 50002
#define KS 9

typedef unsigned long long ull;

// Scratch (device globals: no allocation allowed)
__device__ float g_wt[F_ * KS * E_];   // conv weights transposed [f][k][e]
__device__ float g_h[B_ * F_ * N_];    // tanh(conv) activations, [b][f][n]
__device__ float g_m[B_ * Y_];         // per-row softmax max
__device__ float g_linv[B_ * Y_];      // per-row 1/sum_exp
__device__ float g_loss;               // BCE accumulator

// ---------- packed f32x2 helpers ----------
__device__ __forceinline__ float2 unpack2(ull v) {
    float2 r;
    asm("mov.b64 {%0, %1}, %2;" : "=f"(r.x), "=f"(r.y) : "l"(v));
    return r;
}
__device__ __forceinline__ ull fma2(ull a, ull b, ull c) {
    ull d;
    asm("fma.rn.f32x2 %0, %1, %2, %3;" : "=l"(d) : "l"(a), "l"(b), "l"(c));
    return d;
}

// ---------- K0: transpose conv_w [F][E][K] -> [F][K][E]; zero loss ----------
__global__ void k0_prep(const float* __restrict__ conv_w) {
    int i = blockIdx.x * blockDim.x + threadIdx.x;
    if (i == 0) g_loss = 0.f;
    if (i < F_ * E_ * KS) {
        int f = i / (E_ * KS);
        int r = i % (E_ * KS);
        int e = r / KS;
        int k = r % KS;
        g_wt[f * (KS * E_) + k * E_ + e] = conv_w[i];
    }
}

// ---------- K1: embedding gather + conv1d(SAME) + tanh -> g_h[b][f][n] ----------
#define EPAD 102
__global__ __launch_bounds__(256) void k1_conv(
    const int* __restrict__ x,
    const float* __restrict__ embed_W,
    const float* __restrict__ conv_b)
{
    __shared__ float semb[40 * EPAD];   // rows n0-4 .. n0+35, E values each
    int b  = blockIdx.y;
    int n0 = blockIdx.x * 32;
    int tid = threadIdx.x;

    for (int i = tid; i < 40 * E_; i += 256) {
        int r = i / E_, e = i % E_;
        int n = n0 + r - 4;
        float v = 0.f;
        if (n >= 0 && n < N_) {
            int tok = x[b * N_ + n];
            v = embed_W[tok * E_ + e];
        }
        semb[r * EPAD + e] = v;
    }
    __syncthreads();

    int n_l = tid & 31;
    for (int f = tid >> 5; f < F_; f += 8) {
        ull acc = 0ull;  // (0.f, 0.f)
        #pragma unroll
        for (int k = 0; k < KS; k++) {
            const ull* ep = (const ull*)&semb[(n_l + k) * EPAD];
            const ull* wp = (const ull*)&g_wt[f * (KS * E_) + k * E_];
            #pragma unroll
            for (int e2 = 0; e2 < E_ / 2; e2++)
                acc = fma2(ep[e2], wp[e2], acc);
        }
        float2 a = unpack2(acc);
        float hv = tanhf(a.x + a.y + conv_b[f]);
        if (n0 + n_l < N_)
            g_h[(b * F_ + f) * N_ + n0 + n_l] = hv;
    }
}

// ---------- K2: scores + g, online softmax stats, logits, BCE ----------
// Block: one batch b, 32 labels. 8 warps: warp w -> ygrp = w>>1 (8 labels),
// npart = w&1 (n-pair halves). Each thread owns 2 n-pairs (4 n) x 8 y.
// Raw scores are streamed to the alpha output region (scratch); running
// (max, sumexp, sum exp*g) kept in smem, combined per chunk.
__global__ __launch_bounds__(256, 2) void k2_scores(
    const float* __restrict__ U_w,
    const float* __restrict__ finalW,
    const float* __restrict__ final_bias,
    const float* __restrict__ target,
    float* __restrict__ out)
{
    extern __shared__ float sm[];
    float*  hs   = sm;                                   // [50][256]
    float2* Usd  = (float2*)(sm + F_ * 256);             // [32][50], values duplicated
    float2* Fsd  = Usd + 32 * F_;                        // [32][50]
    float*  sm_m = (float*)(Fsd + 32 * F_);
    float*  sm_l = sm_m + 32;
    float*  sm_a = sm_l + 32;
    float*  red_max = sm_a + 32;                         // [32][2]
    float*  red_sum = red_max + 64;                      // [32][2]
    float*  red_acc = red_sum + 64;                      // [32][2]

    int b   = blockIdx.y;
    int y0  = blockIdx.x * 32;
    int tid = threadIdx.x;
    int w = tid >> 5, lane = tid & 31;
    int ygrp = w >> 1, npart = w & 1;
    int ybl = ygrp * 8;

    // load U / final rows, duplicated per element for f32x2 b-operand
    for (int i = tid; i < 32 * F_; i += 256) {
        int yi = i / F_, f = i % F_;
        int y = y0 + yi;
        float u = 0.f, fn = 0.f;
        if (y < Y_) { u = U_w[y * F_ + f]; fn = finalW[y * F_ + f]; }
        Usd[i] = make_float2(u, u);
        Fsd[i] = make_float2(fn, fn);
    }
    if (tid < 32) { sm_m[tid] = -3.0e38f; sm_l[tid] = 0.f; sm_a[tid] = 0.f; }
    __syncthreads();

    float* alpha = out + (B_ * Y_ + 1);
    int pA = npart * 64 + lane, pB = pA + 32;

    for (int c = 0; c < 10; c++) {
        int n0 = c * 256;
        int nvalid = min(256, N_ - n0);

        for (int i = tid; i < F_ * 256; i += 256) {
            int f = i >> 8, n = i & 255;
            hs[i] = (n < nvalid) ? g_h[(b * F_ + f) * N_ + n0 + n] : 0.f;
        }
        __syncthreads();

        ull sA[8], sB[8], gA[8], gB[8];
        #pragma unroll
        for (int yi = 0; yi < 8; yi++) { sA[yi] = 0; sB[yi] = 0; gA[yi] = 0; gB[yi] = 0; }

        #pragma unroll 2
        for (int f0 = 0; f0 < 48; f0 += 4) {
            ull hA0 = *(const ull*)&hs[(f0 + 0) * 256 + 2 * pA];
            ull hA1 = *(const ull*)&hs[(f0 + 1) * 256 + 2 * pA];
            ull hA2 = *(const ull*)&hs[(f0 + 2) * 256 + 2 * pA];
            ull hA3 = *(const ull*)&hs[(f0 + 3) * 256 + 2 * pA];
            ull hB0 = *(const ull*)&hs[(f0 + 0) * 256 + 2 * pB];
            ull hB1 = *(const ull*)&hs[(f0 + 1) * 256 + 2 * pB];
            ull hB2 = *(const ull*)&hs[(f0 + 2) * 256 + 2 * pB];
            ull hB3 = *(const ull*)&hs[(f0 + 3) * 256 + 2 * pB];
            #pragma unroll
            for (int yi = 0; yi < 8; yi++) {
                int yr = (ybl + yi) * F_;
                ulonglong2 u01 = *(const ulonglong2*)&Usd[yr + f0];
                ulonglong2 u23 = *(const ulonglong2*)&Usd[yr + f0 + 2];
                sA[yi] = fma2(hA0, u01.x, sA[yi]);
                sA[yi] = fma2(hA1, u01.y, sA[yi]);
                sA[yi] = fma2(hA2, u23.x, sA[yi]);
                sA[yi] = fma2(hA3, u23.y, sA[yi]);
                sB[yi] = fma2(hB0, u01.x, sB[yi]);
                sB[yi] = fma2(hB1, u01.y, sB[yi]);
                sB[yi] = fma2(hB2, u23.x, sB[yi]);
                sB[yi] = fma2(hB3, u23.y, sB[yi]);
                ulonglong2 q01 = *(const ulonglong2*)&Fsd[yr + f0];
                ulonglong2 q23 = *(const ulonglong2*)&Fsd[yr + f0 + 2];
                gA[yi] = fma2(hA0, q01.x, gA[yi]);
                gA[yi] = fma2(hA1, q01.y, gA[yi]);
                gA[yi] = fma2(hA2, q23.x, gA[yi]);
                gA[yi] = fma2(hA3, q23.y, gA[yi]);
                gB[yi] = fma2(hB0, q01.x, gB[yi]);
                gB[yi] = fma2(hB1, q01.y, gB[yi]);
                gB[yi] = fma2(hB2, q23.x, gB[yi]);
                gB[yi] = fma2(hB3, q23.y, gB[yi]);
            }
        }
        {   // remainder f = 48, 49
            ull hA0 = *(const ull*)&hs[48 * 256 + 2 * pA];
            ull hA1 = *(const ull*)&hs[49 * 256 + 2 * pA];
            ull hB0 = *(const ull*)&hs[48 * 256 + 2 * pB];
            ull hB1 = *(const ull*)&hs[49 * 256 + 2 * pB];
            #pragma unroll
            for (int yi = 0; yi < 8; yi++) {
                int yr = (ybl + yi) * F_;
                ulonglong2 u = *(const ulonglong2*)&Usd[yr + 48];
                ulonglong2 q = *(const ulonglong2*)&Fsd[yr + 48];
                sA[yi] = fma2(hA0, u.x, sA[yi]);
                sA[yi] = fma2(hA1, u.y, sA[yi]);
                sB[yi] = fma2(hB0, u.x, sB[yi]);
                sB[yi] = fma2(hB1, u.y, sB[yi]);
                gA[yi] = fma2(hA0, q.x, gA[yi]);
                gA[yi] = fma2(hA1, q.y, gA[yi]);
                gB[yi] = fma2(hB0, q.x, gB[yi]);
                gB[yi] = fma2(hB1, q.y, gB[yi]);
            }
        }

        bool vA = (2 * pA < nvalid), vB = (2 * pB < nvalid);

        // phase A: store raw scores, per-y chunk max
        #pragma unroll
        for (int yi = 0; yi < 8; yi++) {
            float2 sa = unpack2(sA[yi]), sb = unpack2(sB[yi]);
            int y = y0 + ybl + yi;
            if (y < Y_) {
                size_t rb = (size_t)(b * Y_ + y) * N_ + n0;
                if (vA) { alpha[rb + 2 * pA] = sa.x; alpha[rb + 2 * pA + 1] = sa.y; }
                if (vB) { alpha[rb + 2 * pB] = sb.x; alpha[rb + 2 * pB + 1] = sb.y; }
            }
            float m1 = vA ? fmaxf(sa.x, sa.y) : -3.0e38f;
            float m2 = vB ? fmaxf(sb.x, sb.y) : -3.0e38f;
            float mv = fmaxf(m1, m2);
            #pragma unroll
            for (int o = 16; o; o >>= 1) mv = fmaxf(mv, __shfl_xor_sync(0xffffffffu, mv, o));
            if (lane == 0) red_max[(ybl + yi) * 2 + npart] = mv;
        }
        __syncthreads();

        // phase B: exp sums + exp*g sums against chunk max
        #pragma unroll
        for (int yi = 0; yi < 8; yi++) {
            float Mc = fmaxf(red_max[(ybl + yi) * 2], red_max[(ybl + yi) * 2 + 1]);
            float2 sa = unpack2(sA[yi]), sb = unpack2(sB[yi]);
            float2 ga = unpack2(gA[yi]), gb = unpack2(gB[yi]);
            float eax = vA ? __expf(sa.x - Mc) : 0.f;
            float eay = vA ? __expf(sa.y - Mc) : 0.f;
            float ebx = vB ? __expf(sb.x - Mc) : 0.f;
            float eby = vB ? __expf(sb.y - Mc) : 0.f;
            float ls = eax + eay + ebx + eby;
            float la = eax * ga.x + eay * ga.y + ebx * gb.x + eby * gb.y;
            #pragma unroll
            for (int o = 16; o; o >>= 1) {
                ls += __shfl_xor_sync(0xffffffffu, ls, o);
                la += __shfl_xor_sync(0xffffffffu, la, o);
            }
            if (lane == 0) {
                red_sum[(ybl + yi) * 2 + npart] = ls;
                red_acc[(ybl + yi) * 2 + npart] = la;
            }
        }
        __syncthreads();

        // phase C: fold chunk stats into running state (online softmax)
        if (tid < 32) {
            float Mc = fmaxf(red_max[tid * 2], red_max[tid * 2 + 1]);
            float S  = red_sum[tid * 2] + red_sum[tid * 2 + 1];
            float A  = red_acc[tid * 2] + red_acc[tid * 2 + 1];
            float mo = sm_m[tid];
            float mn = fmaxf(mo, Mc);
            float so = __expf(mo - mn);
            float sc = __expf(Mc - mn);
            sm_l[tid] = sm_l[tid] * so + S * sc;
            sm_a[tid] = sm_a[tid] * so + A * sc;
            sm_m[tid] = mn;
        }
        __syncthreads();
    }

    // epilogue: logits, yhat, BCE contribution
    if (tid < 32) {
        int y = y0 + tid;
        float li = 0.f;
        if (y < Y_) {
            float m = sm_m[tid], l = sm_l[tid], a = sm_a[tid];
            float logit = a / l + final_bias[y];
            float yh = 1.f / (1.f + __expf(-logit));
            out[b * Y_ + y] = yh;
            g_m[b * Y_ + y] = m;
            g_linv[b * Y_ + y] = 1.f / l;
            float t = target[b * Y_ + y];
            float p = fminf(fmaxf(yh, 1e-7f), 1.f - 1e-7f);
            li = -(t * logf(p) + (1.f - t) * log1pf(-p));
        }
        #pragma unroll
        for (int o = 16; o; o >>= 1) li += __shfl_xor_sync(0xffffffffu, li, o);
        if (tid == 0) atomicAdd(&g_loss, li);
    }
}

// ---------- K3: in-place alpha normalize + loss finalize ----------
__global__ __launch_bounds__(256) void k3_norm(float* __restrict__ out) {
    int row = blockIdx.x;   // b*Y + y
    float m  = g_m[row];
    float il = g_linv[row];
    float* alpha = out + (B_ * Y_ + 1);
    size_t base = (size_t)row * N_;
    for (int i = threadIdx.x; i < N_; i += 256) {
        float s = alpha[base + i];
        alpha[base + i] = __expf(s - m) * il;
    }
    if (blockIdx.x == 0 && threadIdx.x == 0)
        out[B_ * Y_] = g_loss * (1.f / (float)(B_ * Y_));
}

extern "C" void kernel_launch(void* const* d_in, const int* in_sizes, int n_in,
                              void* d_out, int out_size) {
    const int*   x       = (const int*)  d_in[0];
    const float* target  = (const float*)d_in[1];
    const float* embed_W = (const float*)d_in[2];
    const float* conv_w  = (const float*)d_in[3];
    const float* conv_b  = (const float*)d_in[4];
    const float* U_w     = (const float*)d_in[5];
    const float* finalW  = (const float*)d_in[6];
    const float* fbias   = (const float*)d_in[7];
    float* out = (float*)d_out;

    k0_prep<<<(F_ * E_ * KS + 255) / 256, 256>>>(conv_w);
    k1_conv<<<dim3((N_ + 31) / 32, B_), 256>>>(x, embed_W, conv_b);

    int smem_bytes = (F_ * 256) * 4 + 2 * (32 * F_) * 8 + (3 * 32 + 3 * 64) * 4;
    cudaFuncSetAttribute(k2_scores, cudaFuncAttributeMaxDynamicSharedMemorySize, smem_bytes);
    k2_scores<<<dim3((Y_ + 31) / 32, B_), 256, smem_bytes>>>(U_w, finalW, fbias, target, out);

    k3_norm<<<B_ * Y_, 256>>>(out);
}

// round 2
// speedup vs baseline: 1.0417x; 1.0417x over previous
#include <cuda_runtime.h>

#define B_ 8
#define N_ 2500
#define E_ 100
#define F_ 50
#define Y_ 8922
#define V_ 50002
#define KS 9
#define YB 279          // ceil(Y/32)

typedef unsigned long long ull;

// Scratch (device globals: no allocation allowed)
__device__ float g_wt2[KS * E_ * F_];  // conv weights [k][e][f]
__device__ float g_h[B_ * F_ * N_];    // tanh(conv) activations, [b][f][n]
__device__ float g_linv[B_ * Y_];      // per-(b,y) 1/sum_exp
__device__ float g_loss;               // BCE accumulator

// ---------- packed f32x2 helpers ----------
__device__ __forceinline__ float2 unpack2(ull v) {
    float2 r;
    asm("mov.b64 {%0, %1}, %2;" : "=f"(r.x), "=f"(r.y) : "l"(v));
    return r;
}
__device__ __forceinline__ ull pack2(float a, float b) {
    ull r;
    asm("mov.b64 %0, {%1, %2};" : "=l"(r) : "f"(a), "f"(b));
    return r;
}
__device__ __forceinline__ ull fma2(ull a, ull b, ull c) {
    ull d;
    asm("fma.rn.f32x2 %0, %1, %2, %3;" : "=l"(d) : "l"(a), "l"(b), "l"(c));
    return d;
}

// ---------- K0: transpose conv_w [F][E][K] -> [K][E][F]; zero loss ----------
__global__ void k0_prep(const float* __restrict__ conv_w) {
    int i = blockIdx.x * blockDim.x + threadIdx.x;
    if (i == 0) g_loss = 0.f;
    if (i < F_ * E_ * KS) {
        int f = i / (E_ * KS);
        int r = i % (E_ * KS);
        int e = r / KS;
        int k = r % KS;
        g_wt2[(k * E_ + e) * F_ + f] = conv_w[i];
    }
}

// ---------- K1: embedding gather + conv1d(SAME) + tanh -> g_h[b][f][n] ----------
// 128 threads, each owns one output n; all 50 f in 25 f32x2 accumulators.
// Per-k 50x100 weight slice staged into smem, broadcast-read as ull pairs.
#define K1N 128
#define EP 101           // semb row pad (101 mod 32 = 5, coprime -> conflict-free)
#define WSP 26           // ws row pad in ull units (keeps 16B alignment per row)
__global__ __launch_bounds__(K1N) void k1_conv(
    const int* __restrict__ x,
    const float* __restrict__ embed_W,
    const float* __restrict__ conv_b)
{
    __shared__ float semb[(K1N + 8) * EP];   // rows n0-4 .. n0+131
    __shared__ ull   ws[E_ * WSP];           // [e][f-pair]
    __shared__ int   stok[K1N + 8];

    int b   = blockIdx.y;
    int n0  = blockIdx.x * K1N;
    int tid = threadIdx.x;

    for (int r = tid; r < K1N + 8; r += K1N) {
        int n = n0 + r - 4;
        stok[r] = (n >= 0 && n < N_) ? x[b * N_ + n] : -1;
    }
    __syncthreads();

    const float4* embv = (const float4*)embed_W;
    for (int i = tid; i < (K1N + 8) * (E_ / 4); i += K1N) {
        int r  = i / (E_ / 4);
        int c4 = i % (E_ / 4);
        int tok = stok[r];
        float4 v = make_float4(0.f, 0.f, 0.f, 0.f);
        if (tok >= 0) v = embv[tok * (E_ / 4) + c4];
        float* dst = &semb[r * EP + c4 * 4];
        dst[0] = v.x; dst[1] = v.y; dst[2] = v.z; dst[3] = v.w;
    }

    ull acc[F_ / 2];
    #pragma unroll
    for (int fi = 0; fi < F_ / 2; fi++) acc[fi] = 0ull;

    for (int k = 0; k < KS; k++) {
        __syncthreads();   // previous compute done before ws overwrite
        const ull* wsrc = (const ull*)(g_wt2 + k * (E_ * F_));
        for (int i = tid; i < E_ * (F_ / 2); i += K1N) {
            int e = i / (F_ / 2), fi = i % (F_ / 2);
            ws[e * WSP + fi] = wsrc[i];
        }
        __syncthreads();

        const float* srow = &semb[(tid + k) * EP];
        #pragma unroll 4
        for (int e = 0; e < E_; e++) {
            ull hh = pack2(srow[e], srow[e]);
            const ull* w = &ws[e * WSP];
            #pragma unroll
            for (int fi = 0; fi < F_ / 2; fi++)
                acc[fi] = fma2(hh, w[fi], acc[fi]);
        }
    }

    int n = n0 + tid;
    if (n < N_) {
        #pragma unroll
        for (int fi = 0; fi < F_ / 2; fi++) {
            float2 a = unpack2(acc[fi]);
            float h0 = tanhf(a.x + conv_b[2 * fi]);
            float h1 = tanhf(a.y + conv_b[2 * fi + 1]);
            g_h[(b * F_ + 2 * fi)     * N_ + n] = h0;
            g_h[(b * F_ + 2 * fi + 1) * N_ + n] = h1;
        }
    }
}

// ---------- K2a: stats pass — no max needed (scores bounded), no global writes ----------
// Block: batch b x 32 labels. Warp w: ygrp=w>>1 (8 y), npart=w&1.
// Thread owns n-pairs pA, pB (4 n). y processed in 2 groups of 4 to cap registers.
__global__ __launch_bounds__(256, 2) void k2a_stats(
    const float* __restrict__ U_w,
    const float* __restrict__ finalW,
    const float* __restrict__ final_bias,
    const float* __restrict__ target,
    float* __restrict__ out)
{
    extern __shared__ float sm[];
    float*  hs  = sm;                           // [50][256]
    float2* Usd = (float2*)(sm + F_ * 256);     // [32][50] duplicated
    float2* Fsd = Usd + 32 * F_;                // [32][50]
    float*  red_l = (float*)(Fsd + 32 * F_);    // [32][2]
    float*  red_a = red_l + 64;                 // [32][2]

    int b   = blockIdx.y;
    int y0  = blockIdx.x * 32;
    int tid = threadIdx.x;
    int w = tid >> 5, lane = tid & 31;
    int ybl = (w >> 1) * 8, npart = w & 1;
    int pA = npart * 64 + lane, pB = pA + 32;

    for (int i = tid; i < 32 * F_; i += 256) {
        int yi = i / F_, f = i % F_;
        int y = y0 + yi;
        float u = 0.f, fn = 0.f;
        if (y < Y_) { u = U_w[y * F_ + f]; fn = finalW[y * F_ + f]; }
        Usd[i] = make_float2(u, u);
        Fsd[i] = make_float2(fn, fn);
    }

    float lacc[8], aacc[8];
    #pragma unroll
    for (int i = 0; i < 8; i++) { lacc[i] = 0.f; aacc[i] = 0.f; }

    const float4* ghv = (const float4*)g_h;

    for (int c = 0; c < 10; c++) {
        int n0 = c * 256;
        int nvalid = min(256, N_ - n0);
        __syncthreads();   // previous chunk compute done
        if (nvalid == 256) {
            int base = (b * F_) * (N_ / 4) + n0 / 4;
            float4* hv = (float4*)hs;
            for (int v = tid; v < F_ * 64; v += 256) {
                int f = v >> 6, nn = v & 63;
                hv[v] = ghv[base + f * (N_ / 4) + nn];
            }
        } else {
            for (int i = tid; i < F_ * 256; i += 256) {
                int f = i >> 8, nn = i & 255;
                hs[i] = (nn < nvalid) ? g_h[(b * F_ + f) * N_ + n0 + nn] : 0.f;
            }
        }
        __syncthreads();

        bool vA = (2 * pA < nvalid), vB = (2 * pB < nvalid);

        #pragma unroll
        for (int g = 0; g < 2; g++) {
            int yb = ybl + g * 4;
            ull sA[4], sB[4], gA[4], gB[4];
            #pragma unroll
            for (int yi = 0; yi < 4; yi++) { sA[yi] = 0; sB[yi] = 0; gA[yi] = 0; gB[yi] = 0; }

            #pragma unroll 5
            for (int f0 = 0; f0 < F_; f0 += 2) {
                ull hA0 = *(const ull*)&hs[f0 * 256 + 2 * pA];
                ull hA1 = *(const ull*)&hs[(f0 + 1) * 256 + 2 * pA];
                ull hB0 = *(const ull*)&hs[f0 * 256 + 2 * pB];
                ull hB1 = *(const ull*)&hs[(f0 + 1) * 256 + 2 * pB];
                #pragma unroll
                for (int yi = 0; yi < 4; yi++) {
                    ulonglong2 u = *(const ulonglong2*)(Usd + (yb + yi) * F_ + f0);
                    sA[yi] = fma2(hA0, u.x, sA[yi]);
                    sA[yi] = fma2(hA1, u.y, sA[yi]);
                    sB[yi] = fma2(hB0, u.x, sB[yi]);
                    sB[yi] = fma2(hB1, u.y, sB[yi]);
                    ulonglong2 q = *(const ulonglong2*)(Fsd + (yb + yi) * F_ + f0);
                    gA[yi] = fma2(hA0, q.x, gA[yi]);
                    gA[yi] = fma2(hA1, q.y, gA[yi]);
                    gB[yi] = fma2(hB0, q.x, gB[yi]);
                    gB[yi] = fma2(hB1, q.y, gB[yi]);
                }
            }
            #pragma unroll
            for (int yi = 0; yi < 4; yi++) {
                float2 sa = unpack2(sA[yi]), sb = unpack2(sB[yi]);
                float2 ga = unpack2(gA[yi]), gb = unpack2(gB[yi]);
                float eax = vA ? __expf(sa.x) : 0.f;
                float eay = vA ? __expf(sa.y) : 0.f;
                float ebx = vB ? __expf(sb.x) : 0.f;
                float eby = vB ? __expf(sb.y) : 0.f;
                lacc[g * 4 + yi] += (eax + eay) + (ebx + eby);
                aacc[g * 4 + yi] += (eax * ga.x + eay * ga.y) + (ebx * gb.x + eby * gb.y);
            }
        }
    }

    // reduce 32 lanes, then combine the two n-halves
    #pragma unroll
    for (int yi = 0; yi < 8; yi++) {
        float l = lacc[yi], a = aacc[yi];
        #pragma unroll
        for (int o = 16; o; o >>= 1) {
            l += __shfl_xor_sync(0xffffffffu, l, o);
            a += __shfl_xor_sync(0xffffffffu, a, o);
        }
        if (lane == 0) {
            red_l[(ybl + yi) * 2 + npart] = l;
            red_a[(ybl + yi) * 2 + npart] = a;
        }
    }
    __syncthreads();

    if (tid < 32) {
        int y = y0 + tid;
        float li = 0.f;
        if (y < Y_) {
            float l = red_l[tid * 2] + red_l[tid * 2 + 1];
            float a = red_a[tid * 2] + red_a[tid * 2 + 1];
            float logit = a / l + final_bias[y];
            float yh = 1.f / (1.f + __expf(-logit));
            out[b * Y_ + y] = yh;
            g_linv[b * Y_ + y] = 1.f / l;
            float t = target[b * Y_ + y];
            float p = fminf(fmaxf(yh, 1e-7f), 1.f - 1e-7f);
            li = -(t * logf(p) + (1.f - t) * log1pf(-p));
        }
        #pragma unroll
        for (int o = 16; o; o >>= 1) li += __shfl_xor_sync(0xffffffffu, li, o);
        if (tid == 0) atomicAdd(&g_loss, li);
    }
}

// ---------- K2b: alpha pass — recompute scores, write alpha = exp(s)/l ----------
// Same tiling; only the score GEMM. Results staged through smem so global
// stores are 32 consecutive floats per warp (full sector efficiency).
__global__ __launch_bounds__(256, 3) void k2b_alpha(
    const float* __restrict__ U_w,
    float* __restrict__ out)
{
    extern __shared__ float sm[];
    float*  hs  = sm;                           // [50][256], reused as stage [32][256]
    float2* Usd = (float2*)(sm + F_ * 256);     // [32][50]
    float*  slinv = (float*)(Usd + 32 * F_);    // [32]

    int b   = blockIdx.y;
    int y0  = blockIdx.x * 32;
    int tid = threadIdx.x;
    int w = tid >> 5, lane = tid & 31;
    int ybl = (w >> 1) * 8, npart = w & 1;
    int pA = npart * 64 + lane, pB = pA + 32;

    for (int i = tid; i < 32 * F_; i += 256) {
        int yi = i / F_, f = i % F_;
        int y = y0 + yi;
        float u = (y < Y_) ? U_w[y * F_ + f] : 0.f;
        Usd[i] = make_float2(u, u);
    }
    if (tid < 32) {
        int y = y0 + tid;
        slinv[tid] = (y < Y_) ? g_linv[b * Y_ + y] : 0.f;
    }
    __syncthreads();

    float rlinv[8];
    #pragma unroll
    for (int yi = 0; yi < 8; yi++) rlinv[yi] = slinv[ybl + yi];

    const float4* ghv = (const float4*)g_h;
    float* alpha = out + (B_ * Y_ + 1);

    for (int c = 0; c < 10; c++) {
        int n0 = c * 256;
        int nvalid = min(256, N_ - n0);
        __syncthreads();   // previous chunk's staged stores fully read
        if (nvalid == 256) {
            int base = (b * F_) * (N_ / 4) + n0 / 4;
            float4* hv = (float4*)hs;
            for (int v = tid; v < F_ * 64; v += 256) {
                int f = v >> 6, nn = v & 63;
                hv[v] = ghv[base + f * (N_ / 4) + nn];
            }
        } else {
            for (int i = tid; i < F_ * 256; i += 256) {
                int f = i >> 8, nn = i & 255;
                hs[i] = (nn < nvalid) ? g_h[(b * F_ + f) * N_ + n0 + nn] : 0.f;
            }
        }
        __syncthreads();

        ull sA[8], sB[8];
        #pragma unroll
        for (int yi = 0; yi < 8; yi++) { sA[yi] = 0; sB[yi] = 0; }

        #pragma unroll 5
        for (int f0 = 0; f0 < F_; f0 += 2) {
            ull hA0 = *(const ull*)&hs[f0 * 256 + 2 * pA];
            ull hA1 = *(const ull*)&hs[(f0 + 1) * 256 + 2 * pA];
            ull hB0 = *(const ull*)&hs[f0 * 256 + 2 * pB];
            ull hB1 = *(const ull*)&hs[(f0 + 1) * 256 + 2 * pB];
            #pragma unroll
            for (int yi = 0; yi < 8; yi++) {
                ulonglong2 u = *(const ulonglong2*)(Usd + (ybl + yi) * F_ + f0);
                sA[yi] = fma2(hA0, u.x, sA[yi]);
                sA[yi] = fma2(hA1, u.y, sA[yi]);
                sB[yi] = fma2(hB0, u.x, sB[yi]);
                sB[yi] = fma2(hB1, u.y, sB[yi]);
            }
        }
        __syncthreads();   // done reading hs; reuse as stage

        #pragma unroll
        for (int yi = 0; yi < 8; yi++) {
            float2 sa = unpack2(sA[yi]), sb = unpack2(sB[yi]);
            float li = rlinv[yi];
            float ax = __expf(sa.x) * li, ay = __expf(sa.y) * li;
            float bx = __expf(sb.x) * li, by = __expf(sb.y) * li;
            *(float2*)&hs[(ybl + yi) * 256 + 2 * pA] = make_float2(ax, ay);
            *(float2*)&hs[(ybl + yi) * 256 + 2 * pB] = make_float2(bx, by);
        }
        __syncthreads();

        // coalesced scalar stores: warp writes 32 consecutive n of one y row
        #pragma unroll 4
        for (int i = 0; i < 32; i++) {
            int y = y0 + i;
            if (y < Y_ && tid < nvalid)
                alpha[(size_t)(b * Y_ + y) * N_ + n0 + tid] = hs[i * 256 + tid];
        }
    }
}

// ---------- K_fin: finalize loss ----------
__global__ void k_fin(float* __restrict__ out) {
    out[B_ * Y_] = g_loss * (1.f / (float)(B_ * Y_));
}

extern "C" void kernel_launch(void* const* d_in, const int* in_sizes, int n_in,
                              void* d_out, int out_size) {
    const int*   x       = (const int*)  d_in[0];
    const float* target  = (const float*)d_in[1];
    const float* embed_W = (const float*)d_in[2];
    const float* conv_w  = (const float*)d_in[3];
    const float* conv_b  = (const float*)d_in[4];
    const float* U_w     = (const float*)d_in[5];
    const float* finalW  = (const float*)d_in[6];
    const float* fbias   = (const float*)d_in[7];
    float* out = (float*)d_out;

    k0_prep<<<(F_ * E_ * KS + 255) / 256, 256>>>(conv_w);
    k1_conv<<<dim3((N_ + K1N - 1) / K1N, B_), K1N>>>(x, embed_W, conv_b);

    int smem_a = (F_ * 256) * 4 + 2 * (32 * F_) * 8 + 2 * 64 * 4;
    cudaFuncSetAttribute(k2a_stats, cudaFuncAttributeMaxDynamicSharedMemorySize, smem_a);
    k2a_stats<<<dim3(YB, B_), 256, smem_a>>>(U_w, finalW, fbias, target, out);

    k_fin<<<1, 1>>>(out);

    int smem_b = (F_ * 256) * 4 + (32 * F_) * 8 + 32 * 4;
    cudaFuncSetAttribute(k2b_alpha, cudaFuncAttributeMaxDynamicSharedMemorySize, smem_b);
    k2b_alpha<<<dim3(YB, B_), 256, smem_b>>>(U_w, out);
}

// round 4
// speedup vs baseline: 2.5136x; 2.4129x over previous
#include <cuda_runtime.h>
#include <cuda_bf16.h>
#include <cstdint>

#define B_ 8
#define N_ 2500
#define E_ 100
#define F_ 50
#define Y_ 8922
#define KS 9

#define YT 128          // y per CTA
#define NC 128          // n per chunk
#define NCHUNK 20
#define YTILES 70       // ceil(8922/128)

typedef unsigned long long ull;

// ---------------- scratch (device globals) ----------------
__device__ float g_wt2[KS * E_ * F_];          // conv weights [k][e][f]
__device__ uint4 g_hh[B_ * N_ * 8];            // h hi bf16 rows [b*n][64f] (128B rows)
__device__ uint4 g_hl[B_ * N_ * 8];            // h lo bf16 rows
__device__ float g_loss;

// ---------------- packed f32x2 helpers (k1) ----------------
__device__ __forceinline__ float2 unpack2(ull v) {
    float2 r; asm("mov.b64 {%0, %1}, %2;" : "=f"(r.x), "=f"(r.y) : "l"(v)); return r;
}
__device__ __forceinline__ ull pack2(float a, float b) {
    ull r; asm("mov.b64 %0, {%1, %2};" : "=l"(r) : "f"(a), "f"(b)); return r;
}
__device__ __forceinline__ ull fma2(ull a, ull b, ull c) {
    ull d; asm("fma.rn.f32x2 %0, %1, %2, %3;" : "=l"(d) : "l"(a), "l"(b), "l"(c)); return d;
}

// ---------------- mma.sync bf16 (sm_80 baseline PTX; tensor pipe) ----------------
__device__ __forceinline__ void mma_bf16(float* d, const uint32_t* a, uint32_t b0, uint32_t b1) {
    asm volatile("mma.sync.aligned.m16n8k16.row.col.f32.bf16.bf16.f32 "
        "{%0,%1,%2,%3}, {%4,%5,%6,%7}, {%8,%9}, {%0,%1,%2,%3};"
        : "+f"(d[0]), "+f"(d[1]), "+f"(d[2]), "+f"(d[3])
        : "r"(a[0]), "r"(a[1]), "r"(a[2]), "r"(a[3]), "r"(b0), "r"(b1));
}

// hi/lo bf16 split of a float pair -> two packed u32
__device__ __forceinline__ void split2(float v0, float v1, uint32_t& hw, uint32_t& lw) {
    __nv_bfloat16 h0 = __float2bfloat16(v0);
    __nv_bfloat16 h1 = __float2bfloat16(v1);
    __nv_bfloat16 l0 = __float2bfloat16(v0 - __bfloat162float(h0));
    __nv_bfloat16 l1 = __float2bfloat16(v1 - __bfloat162float(h1));
    hw = (uint32_t)*(unsigned short*)&h0 | ((uint32_t)*(unsigned short*)&h1 << 16);
    lw = (uint32_t)*(unsigned short*)&l0 | ((uint32_t)*(unsigned short*)&l1 << 16);
}

// ---------------- K0a / K0b ----------------
__global__ void k0a_zero() { g_loss = 0.f; }

__global__ void k0b_prep(const float* __restrict__ conv_w) {
    int i = blockIdx.x * blockDim.x + threadIdx.x;
    if (i < F_ * E_ * KS) {
        int f = i / (E_ * KS);
        int r = i % (E_ * KS);
        int e = r / KS;
        int k = r % KS;
        g_wt2[(k * E_ + e) * F_ + f] = conv_w[i];
    }
}

// ---------------- K1: embedding + conv1d + tanh -> bf16 hi/lo rows ----------------
#define K1N 128
#define EP 101
#define WSP 26
__global__ __launch_bounds__(K1N) void k1_conv(
    const int* __restrict__ x,
    const float* __restrict__ embed_W,
    const float* __restrict__ conv_b)
{
    __shared__ float semb[(K1N + 8) * EP];
    __shared__ ull   ws[E_ * WSP];
    __shared__ int   stok[K1N + 8];

    int b   = blockIdx.y;
    int n0  = blockIdx.x * K1N;
    int tid = threadIdx.x;

    for (int r = tid; r < K1N + 8; r += K1N) {
        int n = n0 + r - 4;
        stok[r] = (n >= 0 && n < N_) ? x[b * N_ + n] : -1;
    }
    __syncthreads();

    const float4* embv = (const float4*)embed_W;
    for (int i = tid; i < (K1N + 8) * (E_ / 4); i += K1N) {
        int r  = i / (E_ / 4);
        int c4 = i % (E_ / 4);
        int tok = stok[r];
        float4 v = make_float4(0.f, 0.f, 0.f, 0.f);
        if (tok >= 0) v = embv[tok * (E_ / 4) + c4];
        float* dst = &semb[r * EP + c4 * 4];
        dst[0] = v.x; dst[1] = v.y; dst[2] = v.z; dst[3] = v.w;
    }

    ull acc[F_ / 2];
    #pragma unroll
    for (int fi = 0; fi < F_ / 2; fi++) acc[fi] = 0ull;

    for (int k = 0; k < KS; k++) {
        __syncthreads();
        const ull* wsrc = (const ull*)(g_wt2 + k * (E_ * F_));
        for (int i = tid; i < E_ * (F_ / 2); i += K1N) {
            int e = i / (F_ / 2), fi = i % (F_ / 2);
            ws[e * WSP + fi] = wsrc[i];
        }
        __syncthreads();

        const float* srow = &semb[(tid + k) * EP];
        #pragma unroll 4
        for (int e = 0; e < E_; e++) {
            ull hh = pack2(srow[e], srow[e]);
            const ull* w = &ws[e * WSP];
            #pragma unroll
            for (int fi = 0; fi < F_ / 2; fi++)
                acc[fi] = fma2(hh, w[fi], acc[fi]);
        }
    }

    int n = n0 + tid;
    if (n < N_) {
        float hv[64];
        #pragma unroll
        for (int fi = 0; fi < F_ / 2; fi++) {
            float2 a = unpack2(acc[fi]);
            hv[2 * fi]     = tanhf(a.x + conv_b[2 * fi]);
            hv[2 * fi + 1] = tanhf(a.y + conv_b[2 * fi + 1]);
        }
        #pragma unroll
        for (int j = F_; j < 64; j++) hv[j] = 0.f;

        size_t rb = (size_t)(b * N_ + n) * 8;
        #pragma unroll
        for (int s = 0; s < 8; s++) {
            uint32_t hw[4], lw[4];
            #pragma unroll
            for (int p = 0; p < 4; p++)
                split2(hv[s * 8 + p * 2], hv[s * 8 + p * 2 + 1], hw[p], lw[p]);
            g_hh[rb + s] = make_uint4(hw[0], hw[1], hw[2], hw[3]);
            g_hl[rb + s] = make_uint4(lw[0], lw[1], lw[2], lw[3]);
        }
    }
}

// ---------------- K2: fused attention via mma.sync ----------------
// CTA = (128 y, batch b). 8 warps: warp_m = wid&3 (32 y), warp_n = wid>>2 (64 n).
// Per chunk (128 n): s = h·U^T and g = h·final^T via bf16 hi/lo x3 MMA passes.
// Stats (l = sum exp(s), a = sum exp(s)*g) accumulate in registers per y row.
// Pass 2 recomputes s and writes alpha = exp(s)/l via smem stage (coalesced).

// smem byte offsets (rows padded to 144B = 72 bf16 -> conflict-free frag LDS)
#define RSTRIDE 144
#define S_UH 0
#define S_UL 18432
#define S_FH 36864       // pass2: reused as alpha stage (128 x 66 f32)
#define S_FL 55296
#define S_HH 73728
#define S_HL 92160
#define S_RED 110592     // [128 y][8 slots][l,a] f32 = 8192 B
#define S_LINV 118784    // [128] f32
#define SMEM_K2 119296
#define STG_STRIDE 66

__global__ __launch_bounds__(256, 1) void k2_attn(
    const float* __restrict__ U_w,
    const float* __restrict__ finalW,
    const float* __restrict__ fbias,
    const float* __restrict__ target,
    float* __restrict__ out)
{
    extern __shared__ char smem[];
    int tid = threadIdx.x, wid = tid >> 5, lane = tid & 31;
    int gid = lane >> 2, tg = lane & 3;          // mma group / thread-in-group
    int warp_m = wid & 3, warp_n = wid >> 2;
    int b  = blockIdx.y;
    int y0 = blockIdx.x * YT;

    // ---- prologue: U (tid<128) / final (tid>=128) rows -> bf16 hi/lo, padded ----
    {
        int yl = tid & 127;
        const float* src = (tid < 128) ? U_w : finalW;
        int roff = (tid < 128) ? S_UH : S_FH;
        int y = y0 + yl;
        float a[64];
        #pragma unroll
        for (int j = 0; j < 64; j++) a[j] = 0.f;
        if (y < Y_)
            for (int j = 0; j < F_; j++) a[j] = src[(size_t)y * F_ + j];
        #pragma unroll
        for (int s = 0; s < 8; s++) {
            uint32_t hw[4], lw[4];
            #pragma unroll
            for (int p = 0; p < 4; p++)
                split2(a[s * 8 + p * 2], a[s * 8 + p * 2 + 1], hw[p], lw[p]);
            *(uint4*)(smem + roff + yl * RSTRIDE + s * 16)         = make_uint4(hw[0], hw[1], hw[2], hw[3]);
            *(uint4*)(smem + roff + 18432 + yl * RSTRIDE + s * 16) = make_uint4(lw[0], lw[1], lw[2], lw[3]);
        }
    }

    float lacc[4], aacc[4];
    #pragma unroll
    for (int i = 0; i < 4; i++) { lacc[i] = 0.f; aacc[i] = 0.f; }

    // =================== PASS 1: stats ===================
    for (int c = 0; c < NCHUNK; c++) {
        int n0 = c * NC;

        __syncthreads();
        for (int idx = tid; idx < NC * 8; idx += 256) {
            int row = idx >> 3, seg = idx & 7;
            int n = n0 + row;
            uint4 vh = make_uint4(0, 0, 0, 0), vl = make_uint4(0, 0, 0, 0);
            if (n < N_) {
                size_t rbi = (size_t)(b * N_ + n) * 8 + seg;
                vh = g_hh[rbi]; vl = g_hl[rbi];
            }
            *(uint4*)(smem + S_HH + row * RSTRIDE + seg * 16) = vh;
            *(uint4*)(smem + S_HL + row * RSTRIDE + seg * 16) = vl;
        }
        __syncthreads();

        float ds[2][8][4], dg[2][8][4];
        #pragma unroll
        for (int mt = 0; mt < 2; mt++)
            #pragma unroll
            for (int nt = 0; nt < 8; nt++)
                #pragma unroll
                for (int j = 0; j < 4; j++) { ds[mt][nt][j] = 0.f; dg[mt][nt][j] = 0.f; }

        #pragma unroll
        for (int p = 0; p < 3; p++) {
            int aoffU = (p == 2) ? S_UL : S_UH;
            int aoffF = (p == 2) ? S_FL : S_FH;
            int boff  = (p == 1) ? S_HL : S_HH;
            #pragma unroll
            for (int ks = 0; ks < 4; ks++) {
                int kb = ks * 32 + tg * 4;    // byte offset of k pair
                uint32_t au[2][4], af[2][4];
                #pragma unroll
                for (int mt = 0; mt < 2; mt++) {
                    int r0 = (warp_m * 32 + mt * 16 + gid) * RSTRIDE;
                    au[mt][0] = *(const uint32_t*)(smem + aoffU + r0 + kb);
                    au[mt][1] = *(const uint32_t*)(smem + aoffU + r0 + 8 * RSTRIDE + kb);
                    au[mt][2] = *(const uint32_t*)(smem + aoffU + r0 + kb + 16);
                    au[mt][3] = *(const uint32_t*)(smem + aoffU + r0 + 8 * RSTRIDE + kb + 16);
                    af[mt][0] = *(const uint32_t*)(smem + aoffF + r0 + kb);
                    af[mt][1] = *(const uint32_t*)(smem + aoffF + r0 + 8 * RSTRIDE + kb);
                    af[mt][2] = *(const uint32_t*)(smem + aoffF + r0 + kb + 16);
                    af[mt][3] = *(const uint32_t*)(smem + aoffF + r0 + 8 * RSTRIDE + kb + 16);
                }
                #pragma unroll
                for (int nt = 0; nt < 8; nt++) {
                    int br = (warp_n * 64 + nt * 8 + gid) * RSTRIDE;
                    uint32_t b0 = *(const uint32_t*)(smem + boff + br + kb);
                    uint32_t b1 = *(const uint32_t*)(smem + boff + br + kb + 16);
                    mma_bf16(ds[0][nt], au[0], b0, b1);
                    mma_bf16(ds[1][nt], au[1], b0, b1);
                    mma_bf16(dg[0][nt], af[0], b0, b1);
                    mma_bf16(dg[1][nt], af[1], b0, b1);
                }
            }
        }

        // stats epilogue
        if (n0 + NC <= N_) {
            #pragma unroll
            for (int mt = 0; mt < 2; mt++)
                #pragma unroll
                for (int nt = 0; nt < 8; nt++)
                    #pragma unroll
                    for (int j = 0; j < 4; j++) {
                        float e = __expf(ds[mt][nt][j]);
                        lacc[mt * 2 + (j >> 1)] += e;
                        aacc[mt * 2 + (j >> 1)] += e * dg[mt][nt][j];
                    }
        } else {
            #pragma unroll
            for (int mt = 0; mt < 2; mt++)
                #pragma unroll
                for (int nt = 0; nt < 8; nt++)
                    #pragma unroll
                    for (int j = 0; j < 4; j++) {
                        int n = n0 + warp_n * 64 + nt * 8 + tg * 2 + (j & 1);
                        float e = (n < N_) ? __expf(ds[mt][nt][j]) : 0.f;
                        lacc[mt * 2 + (j >> 1)] += e;
                        aacc[mt * 2 + (j >> 1)] += e * dg[mt][nt][j];
                    }
        }
    }

    // ---- cross-warp stats reduction + logits/yhat/BCE ----
    float* red_l = (float*)(smem + S_RED);          // [128][8]
    float* red_a = red_l + 128 * 8;
    float* slinv = (float*)(smem + S_LINV);
    __syncthreads();
    #pragma unroll
    for (int i = 0; i < 4; i++) {
        int y_loc = warp_m * 32 + (i >> 1) * 16 + (i & 1) * 8 + gid;
        red_l[y_loc * 8 + warp_n * 4 + tg] = lacc[i];
        red_a[y_loc * 8 + warp_n * 4 + tg] = aacc[i];
    }
    __syncthreads();
    if (tid < 128) {
        float l = 0.f, a = 0.f;
        #pragma unroll
        for (int s = 0; s < 8; s++) { l += red_l[tid * 8 + s]; a += red_a[tid * 8 + s]; }
        float linv = 1.f / l;
        slinv[tid] = linv;
        int y = y0 + tid;
        float li = 0.f;
        if (y < Y_) {
            float logit = a * linv + fbias[y];
            float yh = 1.f / (1.f + __expf(-logit));
            out[b * Y_ + y] = yh;
            float t = target[b * Y_ + y];
            float p = fminf(fmaxf(yh, 1e-7f), 1.f - 1e-7f);
            li = -(t * logf(p) + (1.f - t) * log1pf(-p));
        }
        #pragma unroll
        for (int o = 16; o; o >>= 1) li += __shfl_xor_sync(0xffffffffu, li, o);
        if (lane == 0) atomicAdd(&g_loss, li);
    }
    __syncthreads();

    float linv4[4];
    #pragma unroll
    for (int i = 0; i < 4; i++)
        linv4[i] = slinv[warp_m * 32 + (i >> 1) * 16 + (i & 1) * 8 + gid];

    // =================== PASS 2: alpha ===================
    float* stage = (float*)(smem + S_FH);   // F region retired: [128][66] f32
    float* alpha = out + (B_ * Y_ + 1);

    for (int c = 0; c < NCHUNK; c++) {
        int n0 = c * NC;

        __syncthreads();
        for (int idx = tid; idx < NC * 8; idx += 256) {
            int row = idx >> 3, seg = idx & 7;
            int n = n0 + row;
            uint4 vh = make_uint4(0, 0, 0, 0), vl = make_uint4(0, 0, 0, 0);
            if (n < N_) {
                size_t rbi = (size_t)(b * N_ + n) * 8 + seg;
                vh = g_hh[rbi]; vl = g_hl[rbi];
            }
            *(uint4*)(smem + S_HH + row * RSTRIDE + seg * 16) = vh;
            *(uint4*)(smem + S_HL + row * RSTRIDE + seg * 16) = vl;
        }
        __syncthreads();

        float ds[2][8][4];
        #pragma unroll
        for (int mt = 0; mt < 2; mt++)
            #pragma unroll
            for (int nt = 0; nt < 8; nt++)
                #pragma unroll
                for (int j = 0; j < 4; j++) ds[mt][nt][j] = 0.f;

        #pragma unroll
        for (int p = 0; p < 3; p++) {
            int aoffU = (p == 2) ? S_UL : S_UH;
            int boff  = (p == 1) ? S_HL : S_HH;
            #pragma unroll
            for (int ks = 0; ks < 4; ks++) {
                int kb = ks * 32 + tg * 4;
                uint32_t au[2][4];
                #pragma unroll
                for (int mt = 0; mt < 2; mt++) {
                    int r0 = (warp_m * 32 + mt * 16 + gid) * RSTRIDE;
                    au[mt][0] = *(const uint32_t*)(smem + aoffU + r0 + kb);
                    au[mt][1] = *(const uint32_t*)(smem + aoffU + r0 + 8 * RSTRIDE + kb);
                    au[mt][2] = *(const uint32_t*)(smem + aoffU + r0 + kb + 16);
                    au[mt][3] = *(const uint32_t*)(smem + aoffU + r0 + 8 * RSTRIDE + kb + 16);
                }
                #pragma unroll
                for (int nt = 0; nt < 8; nt++) {
                    int br = (warp_n * 64 + nt * 8 + gid) * RSTRIDE;
                    uint32_t b0 = *(const uint32_t*)(smem + boff + br + kb);
                    uint32_t b1 = *(const uint32_t*)(smem + boff + br + kb + 16);
                    mma_bf16(ds[0][nt], au[0], b0, b1);
                    mma_bf16(ds[1][nt], au[1], b0, b1);
                }
            }
        }

        // alpha epilogue: two sub-phases, one per warp_n half (stage = 128 x 64)
        #pragma unroll
        for (int q = 0; q < 2; q++) {
            if (warp_n == q) {
                #pragma unroll
                for (int mt = 0; mt < 2; mt++)
                    #pragma unroll
                    for (int nt = 0; nt < 8; nt++)
                        #pragma unroll
                        for (int j = 0; j < 4; j++) {
                            int y_loc = warp_m * 32 + mt * 16 + (j >> 1) * 8 + gid;
                            int nc = nt * 8 + tg * 2 + (j & 1);
                            stage[y_loc * STG_STRIDE + nc] =
                                __expf(ds[mt][nt][j]) * linv4[mt * 2 + (j >> 1)];
                        }
            }
            __syncthreads();
            int nb = n0 + q * 64;
            #pragma unroll 4
            for (int r = 0; r < 16; r++) {
                int y = y0 + wid * 16 + r;
                if (y < Y_) {
                    size_t gb = (size_t)(b * Y_ + y) * N_ + nb;
                    const float* srow = &stage[(wid * 16 + r) * STG_STRIDE];
                    if (nb + lane < N_)      alpha[gb + lane]      = srow[lane];
                    if (nb + lane + 32 < N_) alpha[gb + lane + 32] = srow[lane + 32];
                }
            }
            __syncthreads();
        }
    }
}

// ---------------- K_fin ----------------
__global__ void k_fin(float* __restrict__ out) {
    out[B_ * Y_] = g_loss * (1.f / (float)(B_ * Y_));
}

extern "C" void kernel_launch(void* const* d_in, const int* in_sizes, int n_in,
                              void* d_out, int out_size) {
    const int*   x       = (const int*)  d_in[0];
    const float* target  = (const float*)d_in[1];
    const float* embed_W = (const float*)d_in[2];
    const float* conv_w  = (const float*)d_in[3];
    const float* conv_b  = (const float*)d_in[4];
    const float* U_w     = (const float*)d_in[5];
    const float* finalW  = (const float*)d_in[6];
    const float* fbias   = (const float*)d_in[7];
    float* out = (float*)d_out;

    k0a_zero<<<1, 1>>>();
    k0b_prep<<<(F_ * E_ * KS + 255) / 256, 256>>>(conv_w);
    k1_conv<<<dim3((N_ + K1N - 1) / K1N, B_), K1N>>>(x, embed_W, conv_b);

    cudaFuncSetAttribute(k2_attn, cudaFuncAttributeMaxDynamicSharedMemorySize, SMEM_K2);
    k2_attn<<<dim3(YTILES, B_), 256, SMEM_K2>>>(U_w, finalW, fbias, target, out);

    k_fin<<<1, 1>>>(out);
}